// round 10
// baseline (speedup 1.0000x reference)
#include <cuda_runtime.h>
#include <cuda_fp16.h>
#include <cstdint>

// ---------------- problem constants ----------------
#define DD   1024
#define EE   8
#define HH   4096
#define OO   1024
#define NTOK 4096
#define NPAIR (NTOK * 2)
#define ROWS_CAP (NPAIR + EE * 128)   // 9216

// ---------------- GEMM tile config ----------------
#define BM 128
#define BN 128
#define BK 32        // K elems per chunk = 16 u32 words (fp16 pairs)
#define RW 20        // smem row pitch in u32 (16 data + 4 pad; frag loads conflict-free)

// ---------------- asm / pack helpers ----------------
__device__ __forceinline__ void mma_f16(float* c, const uint32_t* a, const uint32_t* b) {
    asm volatile("mma.sync.aligned.m16n8k16.row.col.f32.f16.f16.f32 "
                 "{%0,%1,%2,%3}, {%4,%5,%6,%7}, {%8,%9}, {%0,%1,%2,%3};"
                 : "+f"(c[0]), "+f"(c[1]), "+f"(c[2]), "+f"(c[3])
                 : "r"(a[0]), "r"(a[1]), "r"(a[2]), "r"(a[3]), "r"(b[0]), "r"(b[1]));
}
__device__ __forceinline__ uint32_t f2h2(float lo, float hi) {
    __half2 h = __floats2half2_rn(lo, hi);   // x = lo (low 16 bits)
    return *(uint32_t*)&h;
}

// ---------------- scratch (static device globals; device-code access ONLY) ----------------
__device__ int   g_counts[EE];
__device__ int   g_cursor[EE];
__device__ int   g_off[EE + 1];
__device__ int   g_top_idx[NPAIR];
__device__ float g_top_w[NPAIR];
__device__ int   g_row_token[ROWS_CAP];
__device__ int   g_row_of_pair[NPAIR];
__device__ __align__(16) __half g_hh[(size_t)ROWS_CAP * HH];       // hidden fp16
__device__ __align__(16) float  g_y[(size_t)ROWS_CAP * OO];
__device__ __align__(16) __half g_w1t[(size_t)EE * HH * DD];       // [E][H][D] fp16
__device__ __align__(16) __half g_w2t[(size_t)EE * OO * HH];       // [E][O][H] fp16

// ---------------- small kernels ----------------
__global__ void init_kernel() {
    int t = threadIdx.x;
    if (t < EE) g_counts[t] = 0;
}

__global__ void router_kernel(const float* __restrict__ x,
                              const float* __restrict__ Wg,
                              const float* __restrict__ bg) {
    __shared__ float sWg[DD * EE];
    int tid = threadIdx.x;
    for (int i = tid * 4; i < DD * EE; i += blockDim.x * 4)
        *(float4*)&sWg[i] = *(const float4*)&Wg[i];
    __syncthreads();

    int warp = tid >> 5, lane = tid & 31;
    int n = blockIdx.x * 8 + warp;
    const float* xr = x + (size_t)n * DD;

    float acc[EE];
#pragma unroll
    for (int e = 0; e < EE; e++) acc[e] = 0.f;
    for (int d = lane; d < DD; d += 32) {
        float xv = xr[d];
#pragma unroll
        for (int e = 0; e < EE; e++) acc[e] += xv * sWg[d * EE + e];
    }
#pragma unroll
    for (int e = 0; e < EE; e++)
#pragma unroll
        for (int s = 16; s; s >>= 1) acc[e] += __shfl_xor_sync(0xffffffffu, acc[e], s);

    if (lane == 0) {
        float m = -1e30f;
#pragma unroll
        for (int e = 0; e < EE; e++) { acc[e] += bg[e]; m = fmaxf(m, acc[e]); }
        float s = 0.f;
#pragma unroll
        for (int e = 0; e < EE; e++) { acc[e] = __expf(acc[e] - m); s += acc[e]; }
        float inv = 1.f / s;
        int i0 = 0; float p0 = acc[0];
#pragma unroll
        for (int e = 1; e < EE; e++) if (acc[e] > p0) { p0 = acc[e]; i0 = e; }
        int i1 = -1; float p1 = -1.f;
#pragma unroll
        for (int e = 0; e < EE; e++) if (e != i0 && acc[e] > p1) { p1 = acc[e]; i1 = e; }

        g_top_idx[2 * n]     = i0; g_top_w[2 * n]     = p0 * inv;
        g_top_idx[2 * n + 1] = i1; g_top_w[2 * n + 1] = p1 * inv;
        atomicAdd(&g_counts[i0], 1);
        atomicAdd(&g_counts[i1], 1);
    }
}

__global__ void scan_kernel() {
    int off = 0;
    for (int e = 0; e < EE; e++) {
        g_off[e] = off;
        g_cursor[e] = off;
        off += (g_counts[e] + 127) & ~127;
    }
    g_off[EE] = off;
}

__global__ void scatter_kernel() {
    int p = blockIdx.x * blockDim.x + threadIdx.x;
    if (p >= NPAIR) return;
    int e = g_top_idx[p];
    int pos = atomicAdd(&g_cursor[e], 1);
    g_row_token[pos] = p >> 1;
    g_row_of_pair[p] = pos;
}

// Transpose + fp16 convert: W [E][R][C] (C contiguous) -> T fp16 [E][C][R].
// sel chooses destination GLOBAL in device code.
__global__ void transpose_cvt_kernel(const float* __restrict__ W,
                                     int sel, int R, int C) {
    __half* __restrict__ T = (sel == 1) ? g_w1t : g_w2t;
    __shared__ float t[32][33];
    int e = blockIdx.z;
    int c0 = blockIdx.x * 32, r0 = blockIdx.y * 32;
    const float* Wp = W + (size_t)e * R * C;
    int tid = threadIdx.x;
#pragma unroll
    for (int i = 0; i < 4; i++) {
        int idx = tid + 256 * i;
        int rr = idx >> 5, cc = idx & 31;
        t[rr][cc] = Wp[(size_t)(r0 + rr) * C + c0 + cc];
    }
    __syncthreads();
    // out row oc (c-dim), 4 consecutive out-cols 4g..4g+3 (r-dim)
    int oc = tid >> 3, g = tid & 7;
    uint2 o;
    o.x = f2h2(t[4 * g + 0][oc], t[4 * g + 1][oc]);
    o.y = f2h2(t[4 * g + 2][oc], t[4 * g + 3][oc]);
    *(uint2*)(T + ((size_t)e * C + c0 + oc) * (size_t)R + r0 + 4 * g) = o;
}

// ---------------- FP16 grouped GEMM (single product, fp32 accumulate) ----------------
// GEMM1: A = gathered x fp32 (cvt at smem store), B = g_w1t fp16 -> g_hh fp16 (relu)
// GEMM2: A = g_hh fp16 (direct copy), B = g_w2t fp16 -> g_y fp32
template <int KTOT, int NOUTT, bool G1>
__global__ __launch_bounds__(256, 1) void moe_gemm(const float* __restrict__ xArg,
                                                   const float* __restrict__ bias) {
    const __half* __restrict__ Bw = G1 ? g_w1t : g_w2t;

    __shared__ __align__(16) uint32_t sA[BM][RW];   // [m][k-pair words]
    __shared__ __align__(16) uint32_t sB[BN][RW];   // [n][k-pair words]
    __shared__ int stok[BM];

    const int tid = threadIdx.x;
    const int row0 = blockIdx.y * BM;
    if (row0 >= g_off[EE]) return;
    int e = 0;
#pragma unroll
    for (int i = 1; i < EE; i++) if (row0 >= g_off[i]) e = i;
    const int valid = g_off[e] + g_counts[e] - row0;
    const int n0 = blockIdx.x * BN;

    if (G1) {
        if (tid < BM) stok[tid] = (tid < valid) ? g_row_token[row0 + tid] : -1;
        __syncthreads();
    }

    // ---- loader slots ----
    // G1 A (fp32 gather): 4 slots, r=id>>3, ch=id&7; float4 -> uint2 at word ch*2
    const float* aF[4]; uint32_t* adF[4]; bool aok[4];
    // !G1 A (fp16 rows): 2 slots, r=id>>2, c4=id&3; uint4 (8 fp16) at word c4*4
    const __half* aH[2]; uint32_t* adH[2];
    if (G1) {
#pragma unroll
        for (int j = 0; j < 4; j++) {
            int id = tid + 256 * j;
            int r = id >> 3, ch = id & 7;
            int tk = stok[r];
            aok[j] = (tk >= 0);
            long ar = aok[j] ? tk : 0;
            aF[j] = xArg + (size_t)ar * KTOT + ch * 4;
            adF[j] = &sA[r][ch * 2];
        }
    } else {
#pragma unroll
        for (int j = 0; j < 2; j++) {
            int id = tid + 256 * j;
            int r = id >> 2, c4 = id & 3;
            aH[j] = g_hh + (size_t)(row0 + r) * KTOT + c4 * 8;
            adH[j] = &sA[r][c4 * 4];
        }
    }
    // B (fp16 [E][N][K]): 2 slots, r=id>>2, c4=id&3
    const __half* bS[2]; uint32_t* bd[2];
#pragma unroll
    for (int j = 0; j < 2; j++) {
        int id = tid + 256 * j;
        int r = id >> 2, c4 = id & 3;
        bS[j] = Bw + ((size_t)(e * NOUTT + n0 + r)) * KTOT + c4 * 8;
        bd[j] = &sB[r][c4 * 4];
    }

    const int lane = tid & 31, wid = tid >> 5;
    const int wm = (wid >> 2) * 64, wn = (wid & 3) * 32;
    const int gid = lane >> 2, tg = lane & 3;

    float acc[4][4][4];
#pragma unroll
    for (int i = 0; i < 4; i++)
#pragma unroll
        for (int j = 0; j < 4; j++)
#pragma unroll
            for (int q = 0; q < 4; q++) acc[i][j][q] = 0.f;

    const int NC = KTOT / BK;
    const float4 zf4 = make_float4(0.f, 0.f, 0.f, 0.f);
    float4 paF[4]; uint4 paH[2]; uint4 pbv[2];
    if (G1) {
#pragma unroll
        for (int j = 0; j < 4; j++) paF[j] = aok[j] ? *(const float4*)aF[j] : zf4;
    } else {
#pragma unroll
        for (int j = 0; j < 2; j++) paH[j] = *(const uint4*)aH[j];
    }
#pragma unroll
    for (int j = 0; j < 2; j++) pbv[j] = *(const uint4*)bS[j];

#pragma unroll 1
    for (int c = 0; c < NC; c++) {
        __syncthreads();   // previous iter's smem reads done before overwrite
        if (G1) {
#pragma unroll
            for (int j = 0; j < 4; j++) {
                uint2 u;
                u.x = f2h2(paF[j].x, paF[j].y);
                u.y = f2h2(paF[j].z, paF[j].w);
                *(uint2*)adF[j] = u;
            }
        } else {
#pragma unroll
            for (int j = 0; j < 2; j++) *(uint4*)adH[j] = paH[j];
        }
#pragma unroll
        for (int j = 0; j < 2; j++) *(uint4*)bd[j] = pbv[j];
        __syncthreads();
        if (c + 1 < NC) {  // prefetch next K-slab into regs (hidden by MMAs)
            size_t ko = (size_t)(c + 1) * BK;
            if (G1) {
#pragma unroll
                for (int j = 0; j < 4; j++)
                    paF[j] = aok[j] ? *(const float4*)(aF[j] + ko) : zf4;
            } else {
#pragma unroll
                for (int j = 0; j < 2; j++) paH[j] = *(const uint4*)(aH[j] + ko);
            }
#pragma unroll
            for (int j = 0; j < 2; j++) pbv[j] = *(const uint4*)(bS[j] + ko);
        }
#pragma unroll
        for (int kk = 0; kk < 2; kk++) {
            const int kb = kk * 8;   // 8 words = 16 fp16 = one k16 step
            // A frags: a0:(gid, word kb+tg) a1:(gid+8) a2:(gid, kb+4+tg) a3:(gid+8)
            uint32_t af[4][4];
#pragma unroll
            for (int mt = 0; mt < 4; mt++) {
                int r = wm + mt * 16 + gid;
                af[mt][0] = sA[r][kb + tg];
                af[mt][1] = sA[r + 8][kb + tg];
                af[mt][2] = sA[r][kb + 4 + tg];
                af[mt][3] = sA[r + 8][kb + 4 + tg];
            }
            // B frags from [n][k]: b0 = word kb+tg of row n, b1 = kb+4+tg
            uint32_t bf[4][2];
#pragma unroll
            for (int nt = 0; nt < 4; nt++) {
                int n = wn + nt * 8 + gid;
                bf[nt][0] = sB[n][kb + tg];
                bf[nt][1] = sB[n][kb + 4 + tg];
            }
#pragma unroll
            for (int mt = 0; mt < 4; mt++)
#pragma unroll
                for (int nt = 0; nt < 4; nt++)
                    mma_f16(acc[mt][nt], af[mt], bf[nt]);
        }
    }

    // ---------------- epilogue (C frag: c0/c1 row gid cols 2tg,2tg+1; c2/c3 row gid+8) ----------------
#pragma unroll
    for (int mt = 0; mt < 4; mt++) {
#pragma unroll
        for (int nt = 0; nt < 4; nt++) {
            int mm = wm + mt * 16 + gid;          // block-local row
            int m = row0 + mm;
            int n = n0 + wn + nt * 8 + 2 * tg;
            float b0 = bias[(size_t)e * NOUTT + n];
            float b1v = bias[(size_t)e * NOUTT + n + 1];
            float z00 = acc[mt][nt][0] + b0, z01 = acc[mt][nt][1] + b1v;
            float z10 = acc[mt][nt][2] + b0, z11 = acc[mt][nt][3] + b1v;
            if (G1) {
                z00 = fmaxf(z00, 0.f); z01 = fmaxf(z01, 0.f);
                z10 = fmaxf(z10, 0.f); z11 = fmaxf(z11, 0.f);
                if (mm < valid)
                    *(uint32_t*)(g_hh + (size_t)m * NOUTT + n) = f2h2(z00, z01);
                if (mm + 8 < valid)
                    *(uint32_t*)(g_hh + (size_t)(m + 8) * NOUTT + n) = f2h2(z10, z11);
            } else {
                if (mm < valid)
                    *(float2*)(g_y + (size_t)m * NOUTT + n) = make_float2(z00, z01);
                if (mm + 8 < valid)
                    *(float2*)(g_y + (size_t)(m + 8) * NOUTT + n) = make_float2(z10, z11);
            }
        }
    }
}

// ---------------- combine ----------------
__global__ void combine_kernel(float* __restrict__ out) {
    int n = blockIdx.x;
    int r0 = g_row_of_pair[2 * n];
    int r1 = g_row_of_pair[2 * n + 1];
    float w0 = g_top_w[2 * n];
    float w1 = g_top_w[2 * n + 1];
    const float4* y0 = (const float4*)&g_y[(size_t)r0 * OO];
    const float4* y1 = (const float4*)&g_y[(size_t)r1 * OO];
    float4* o = (float4*)&out[(size_t)n * OO];
    int t = threadIdx.x;
    float4 a = y0[t], b = y1[t];
    float4 r;
    r.x = w0 * a.x + w1 * b.x;
    r.y = w0 * a.y + w1 * b.y;
    r.z = w0 * a.z + w1 * b.z;
    r.w = w0 * a.w + w1 * b.w;
    o[t] = r;
}

// ---------------- launch ----------------
extern "C" void kernel_launch(void* const* d_in, const int* in_sizes, int n_in,
                              void* d_out, int out_size) {
    const float* x  = (const float*)d_in[0];
    const float* Wg = (const float*)d_in[1];
    const float* bg = (const float*)d_in[2];
    const float* W1 = (const float*)d_in[3];
    const float* b1 = (const float*)d_in[4];
    const float* W2 = (const float*)d_in[5];
    const float* b2 = (const float*)d_in[6];
    float* out = (float*)d_out;

    init_kernel<<<1, 32>>>();
    router_kernel<<<NTOK / 8, 256>>>(x, Wg, bg);
    scan_kernel<<<1, 1>>>();
    scatter_kernel<<<NPAIR / 256, 256>>>();

    transpose_cvt_kernel<<<dim3(HH / 32, DD / 32, EE), 256>>>(W1, 1, DD, HH);
    transpose_cvt_kernel<<<dim3(OO / 32, HH / 32, EE), 256>>>(W2, 2, HH, OO);

    moe_gemm<DD, HH, true><<<dim3(HH / BN, ROWS_CAP / BM), 256>>>(x, b1);
    moe_gemm<HH, OO, false><<<dim3(OO / BN, ROWS_CAP / BM), 256>>>(x, b2);

    combine_kernel<<<NTOK, 256>>>(out);
}

// round 11
// speedup vs baseline: 1.2278x; 1.2278x over previous
#include <cuda_runtime.h>
#include <cuda_fp16.h>
#include <cstdint>

// ---------------- problem constants ----------------
#define DD   1024
#define EE   8
#define HH   4096
#define OO   1024
#define NTOK 4096
#define NPAIR (NTOK * 2)
#define ROWS_CAP (NPAIR + EE * 128)   // 9216

// ---------------- GEMM tile config ----------------
#define BM 128
#define BN 128
#define BK 32
#define RWA 36       // A smem pitch (u32): frag loads conflict-free
#define RWB 136      // B smem pitch (u32): 136%32==8 -> frag loads conflict-free

// ---------------- asm helpers ----------------
__device__ __forceinline__ void mma_tf32(float* c, const uint32_t* a, const uint32_t* b) {
    asm volatile("mma.sync.aligned.m16n8k8.row.col.f32.tf32.tf32.f32 "
                 "{%0,%1,%2,%3}, {%4,%5,%6,%7}, {%8,%9}, {%0,%1,%2,%3};"
                 : "+f"(c[0]), "+f"(c[1]), "+f"(c[2]), "+f"(c[3])
                 : "r"(a[0]), "r"(a[1]), "r"(a[2]), "r"(a[3]), "r"(b[0]), "r"(b[1]));
}
__device__ __forceinline__ uint32_t f2tf32(float v) {
    uint32_t r;
    asm("cvt.rna.tf32.f32 %0, %1;" : "=r"(r) : "f"(v));
    return r;
}
__device__ __forceinline__ uint4 cvt4(float4 v) {
    uint4 o;
    o.x = f2tf32(v.x); o.y = f2tf32(v.y);
    o.z = f2tf32(v.z); o.w = f2tf32(v.w);
    return o;
}
__device__ __forceinline__ uint32_t f2h2(float lo, float hi) {
    __half2 h = __floats2half2_rn(lo, hi);
    return *(uint32_t*)&h;
}

// ---------------- scratch (static device globals; device-code access ONLY) ----------------
__device__ int   g_counts[EE];
__device__ int   g_cursor[EE];
__device__ int   g_off[EE + 1];
__device__ int   g_top_idx[NPAIR];
__device__ float g_top_w[NPAIR];
__device__ int   g_row_token[ROWS_CAP];
__device__ int   g_row_of_pair[NPAIR];
__device__ __align__(16) __half g_hf16[(size_t)ROWS_CAP * HH];   // hidden, fp16 (11-bit = tf32 mantissa)
__device__ __align__(16) float  g_y[(size_t)ROWS_CAP * OO];

// ---------------- small kernels ----------------
__global__ void init_kernel() {
    int t = threadIdx.x;
    if (t < EE) g_counts[t] = 0;
}

__global__ void router_kernel(const float* __restrict__ x,
                              const float* __restrict__ Wg,
                              const float* __restrict__ bg) {
    __shared__ float sWg[DD * EE];
    int tid = threadIdx.x;
    for (int i = tid * 4; i < DD * EE; i += blockDim.x * 4)
        *(float4*)&sWg[i] = *(const float4*)&Wg[i];
    __syncthreads();

    int warp = tid >> 5, lane = tid & 31;
    int n = blockIdx.x * 8 + warp;
    const float* xr = x + (size_t)n * DD;

    float acc[EE];
#pragma unroll
    for (int e = 0; e < EE; e++) acc[e] = 0.f;
    for (int d = lane; d < DD; d += 32) {
        float xv = xr[d];
#pragma unroll
        for (int e = 0; e < EE; e++) acc[e] += xv * sWg[d * EE + e];
    }
#pragma unroll
    for (int e = 0; e < EE; e++)
#pragma unroll
        for (int s = 16; s; s >>= 1) acc[e] += __shfl_xor_sync(0xffffffffu, acc[e], s);

    if (lane == 0) {
        float m = -1e30f;
#pragma unroll
        for (int e = 0; e < EE; e++) { acc[e] += bg[e]; m = fmaxf(m, acc[e]); }
        float s = 0.f;
#pragma unroll
        for (int e = 0; e < EE; e++) { acc[e] = __expf(acc[e] - m); s += acc[e]; }
        float inv = 1.f / s;
        int i0 = 0; float p0 = acc[0];
#pragma unroll
        for (int e = 1; e < EE; e++) if (acc[e] > p0) { p0 = acc[e]; i0 = e; }
        int i1 = -1; float p1 = -1.f;
#pragma unroll
        for (int e = 0; e < EE; e++) if (e != i0 && acc[e] > p1) { p1 = acc[e]; i1 = e; }

        g_top_idx[2 * n]     = i0; g_top_w[2 * n]     = p0 * inv;
        g_top_idx[2 * n + 1] = i1; g_top_w[2 * n + 1] = p1 * inv;
        atomicAdd(&g_counts[i0], 1);
        atomicAdd(&g_counts[i1], 1);
    }
}

__global__ void scan_kernel() {
    int off = 0;
    for (int e = 0; e < EE; e++) {
        g_off[e] = off;
        g_cursor[e] = off;
        off += (g_counts[e] + 127) & ~127;
    }
    g_off[EE] = off;
}

__global__ void scatter_kernel() {
    int p = blockIdx.x * blockDim.x + threadIdx.x;
    if (p >= NPAIR) return;
    int e = g_top_idx[p];
    int pos = atomicAdd(&g_cursor[e], 1);
    g_row_token[pos] = p >> 1;
    g_row_of_pair[p] = pos;
}

// ---------------- TF32 grouped GEMM, fused on-the-fly rounding ----------------
// B (fp32 weights [E][K][N], N contiguous) read raw, tf32-rounded at smem store,
// staged [k][n] pitch 136. A: GEMM1 = gathered fp32 x (tf32 cvt at store);
// GEMM2 = fp16 hidden rows (exact cvt to fp32 = already tf32-representable).
// GEMM1 out: relu -> fp16 g_hf16.  GEMM2 out: fp32 g_y.
template <int KTOT, int NOUTT, bool G1>
__global__ __launch_bounds__(256, 1) void moe_gemm(const float* __restrict__ xArg,
                                                   const float* __restrict__ Barg,
                                                   const float* __restrict__ bias) {
    const int NOUT = NOUTT;

    __shared__ __align__(16) uint32_t sA[BM][RWA];     // [m][k] fp32(tf32)
    __shared__ __align__(16) uint32_t sB[BK][RWB];     // [k][n] fp32(tf32)
    __shared__ int stok[BM];

    const int tid = threadIdx.x;
    const int row0 = blockIdx.y * BM;
    if (row0 >= g_off[EE]) return;
    int e = 0;
#pragma unroll
    for (int i = 1; i < EE; i++) if (row0 >= g_off[i]) e = i;
    const int valid = g_off[e] + g_counts[e] - row0;
    const int n0 = blockIdx.x * BN;
    const float* __restrict__ Bbase = Barg + (size_t)e * KTOT * NOUT + n0;

    if (G1) {
        if (tid < BM) stok[tid] = (tid < valid) ? g_row_token[row0 + tid] : -1;
        __syncthreads();
    }

    // ---- loader slots ----
    // G1 A (fp32 gather): 4 slots, r=id>>3, ch=id&7 (float4 chunks)
    const float* aF[4]; uint32_t* adF[4]; bool aok[4];
    // G2 A (fp16 rows): 2 slots, r=id>>2, c8=id&3 (8-half chunks)
    const __half* aH[2]; uint32_t* adH[2];
    if (G1) {
#pragma unroll
        for (int j = 0; j < 4; j++) {
            int id = tid + 256 * j;
            int r = id >> 3, ch = id & 7;
            int tk = stok[r];
            aok[j] = (tk >= 0);
            long ar = aok[j] ? tk : 0;
            aF[j] = xArg + (size_t)ar * KTOT + ch * 4;
            adF[j] = &sA[r][ch * 4];
        }
    } else {
#pragma unroll
        for (int j = 0; j < 2; j++) {
            int id = tid + 256 * j;
            int r = id >> 2, c8 = id & 3;
            aH[j] = g_hf16 + (size_t)(row0 + r) * KTOT + c8 * 8;
            adH[j] = &sA[r][c8 * 8];
        }
    }
    // B slots: kq = id>>5 (k-row), nq = id&31 (n-chunk of 4)
    const float* bsrc[4]; uint32_t* bdst[4];
#pragma unroll
    for (int j = 0; j < 4; j++) {
        int id = tid + 256 * j;
        int kq = id >> 5, nq = id & 31;
        bsrc[j] = Bbase + (size_t)kq * NOUT + nq * 4;
        bdst[j] = &sB[kq][nq * 4];
    }

    const int lane = tid & 31, wid = tid >> 5;
    const int wm = (wid >> 2) * 64, wn = (wid & 3) * 32;
    const int gid = lane >> 2, tg = lane & 3;

    float acc[4][4][4];
#pragma unroll
    for (int i = 0; i < 4; i++)
#pragma unroll
        for (int j = 0; j < 4; j++)
#pragma unroll
            for (int q = 0; q < 4; q++) acc[i][j][q] = 0.f;

    const int NC = KTOT / BK;
    const float4 zf4 = make_float4(0.f, 0.f, 0.f, 0.f);
    float4 paF[4]; uint4 paH[2]; float4 pb[4];
    if (G1) {
#pragma unroll
        for (int j = 0; j < 4; j++) paF[j] = aok[j] ? *(const float4*)aF[j] : zf4;
    } else {
#pragma unroll
        for (int j = 0; j < 2; j++) paH[j] = *(const uint4*)aH[j];
    }
#pragma unroll
    for (int j = 0; j < 4; j++) pb[j] = *(const float4*)bsrc[j];

#pragma unroll 1
    for (int c = 0; c < NC; c++) {
        __syncthreads();   // previous iter's smem reads done before overwrite
        if (G1) {
#pragma unroll
            for (int j = 0; j < 4; j++) *(uint4*)adF[j] = cvt4(paF[j]);
        } else {
#pragma unroll
            for (int j = 0; j < 2; j++) {
                // 8 halves -> 8 floats (exact; fp16 mantissa == tf32 mantissa)
                __half2 h0 = *(__half2*)&paH[j].x;
                __half2 h1 = *(__half2*)&paH[j].y;
                __half2 h2 = *(__half2*)&paH[j].z;
                __half2 h3 = *(__half2*)&paH[j].w;
                float2 f0 = __half22float2(h0);
                float2 f1 = __half22float2(h1);
                float2 f2 = __half22float2(h2);
                float2 f3 = __half22float2(h3);
                uint4 lo, hi;
                lo.x = __float_as_uint(f0.x); lo.y = __float_as_uint(f0.y);
                lo.z = __float_as_uint(f1.x); lo.w = __float_as_uint(f1.y);
                hi.x = __float_as_uint(f2.x); hi.y = __float_as_uint(f2.y);
                hi.z = __float_as_uint(f3.x); hi.w = __float_as_uint(f3.y);
                *(uint4*)adH[j] = lo;
                *(uint4*)(adH[j] + 4) = hi;
            }
        }
#pragma unroll
        for (int j = 0; j < 4; j++) *(uint4*)bdst[j] = cvt4(pb[j]);
        __syncthreads();
        if (c + 1 < NC) {  // prefetch next K-slab into regs (hidden by MMAs)
            size_t ko = (size_t)(c + 1) * BK;
            if (G1) {
#pragma unroll
                for (int j = 0; j < 4; j++)
                    paF[j] = aok[j] ? *(const float4*)(aF[j] + ko) : zf4;
            } else {
#pragma unroll
                for (int j = 0; j < 2; j++) paH[j] = *(const uint4*)(aH[j] + ko);
            }
#pragma unroll
            for (int j = 0; j < 4; j++) pb[j] = *(const float4*)(bsrc[j] + ko * NOUT);
        }
#pragma unroll
        for (int kk = 0; kk < 4; kk++) {
            const int kb = kk * 8;   // 8 fp32 = K8 per mma step
            // A frags (m16n8k8): a0:(gid,tg) a1:(gid+8,tg) a2:(gid,tg+4) a3:(gid+8,tg+4)
            uint32_t af[4][4];
#pragma unroll
            for (int mt = 0; mt < 4; mt++) {
                int r = wm + mt * 16 + gid;
                af[mt][0] = sA[r][kb + tg];
                af[mt][1] = sA[r + 8][kb + tg];
                af[mt][2] = sA[r][kb + 4 + tg];
                af[mt][3] = sA[r + 8][kb + 4 + tg];
            }
            // B frags from [k][n]: b0 = (k=kb+tg, n), b1 = (k=kb+4+tg, n)
            uint32_t bf[4][2];
#pragma unroll
            for (int nt = 0; nt < 4; nt++) {
                int n = wn + nt * 8 + gid;
                bf[nt][0] = sB[kb + tg][n];
                bf[nt][1] = sB[kb + 4 + tg][n];
            }
#pragma unroll
            for (int mt = 0; mt < 4; mt++)
#pragma unroll
                for (int nt = 0; nt < 4; nt++)
                    mma_tf32(acc[mt][nt], af[mt], bf[nt]);
        }
    }

    // ---------------- epilogue (C frag: c0/c1 row gid cols 2tg,2tg+1; c2/c3 row gid+8) ----------------
#pragma unroll
    for (int mt = 0; mt < 4; mt++) {
#pragma unroll
        for (int nt = 0; nt < 4; nt++) {
            int mm = wm + mt * 16 + gid;          // block-local row
            int m = row0 + mm;
            int n = n0 + wn + nt * 8 + 2 * tg;
            float b0 = bias[(size_t)e * NOUT + n];
            float b1v = bias[(size_t)e * NOUT + n + 1];
            float z00 = acc[mt][nt][0] + b0, z01 = acc[mt][nt][1] + b1v;
            float z10 = acc[mt][nt][2] + b0, z11 = acc[mt][nt][3] + b1v;
            if (G1) {
                z00 = fmaxf(z00, 0.f); z01 = fmaxf(z01, 0.f);
                z10 = fmaxf(z10, 0.f); z11 = fmaxf(z11, 0.f);
                if (mm < valid)
                    *(uint32_t*)(g_hf16 + (size_t)m * NOUT + n) = f2h2(z00, z01);
                if (mm + 8 < valid)
                    *(uint32_t*)(g_hf16 + (size_t)(m + 8) * NOUT + n) = f2h2(z10, z11);
            } else {
                if (mm < valid)
                    *(float2*)(g_y + (size_t)m * NOUT + n) = make_float2(z00, z01);
                if (mm + 8 < valid)
                    *(float2*)(g_y + (size_t)(m + 8) * NOUT + n) = make_float2(z10, z11);
            }
        }
    }
}

// ---------------- combine ----------------
__global__ void combine_kernel(float* __restrict__ out) {
    int n = blockIdx.x;
    int r0 = g_row_of_pair[2 * n];
    int r1 = g_row_of_pair[2 * n + 1];
    float w0 = g_top_w[2 * n];
    float w1 = g_top_w[2 * n + 1];
    const float4* y0 = (const float4*)&g_y[(size_t)r0 * OO];
    const float4* y1 = (const float4*)&g_y[(size_t)r1 * OO];
    float4* o = (float4*)&out[(size_t)n * OO];
    int t = threadIdx.x;
    float4 a = y0[t], b = y1[t];
    float4 r;
    r.x = w0 * a.x + w1 * b.x;
    r.y = w0 * a.y + w1 * b.y;
    r.z = w0 * a.z + w1 * b.z;
    r.w = w0 * a.w + w1 * b.w;
    o[t] = r;
}

// ---------------- launch ----------------
extern "C" void kernel_launch(void* const* d_in, const int* in_sizes, int n_in,
                              void* d_out, int out_size) {
    const float* x  = (const float*)d_in[0];
    const float* Wg = (const float*)d_in[1];
    const float* bg = (const float*)d_in[2];
    const float* W1 = (const float*)d_in[3];
    const float* b1 = (const float*)d_in[4];
    const float* W2 = (const float*)d_in[5];
    const float* b2 = (const float*)d_in[6];
    float* out = (float*)d_out;

    init_kernel<<<1, 32>>>();
    router_kernel<<<NTOK / 8, 256>>>(x, Wg, bg);
    scan_kernel<<<1, 1>>>();
    scatter_kernel<<<NPAIR / 256, 256>>>();

    moe_gemm<DD, HH, true><<<dim3(HH / BN, ROWS_CAP / BM), 256>>>(x, W1, b1);
    moe_gemm<HH, OO, false><<<dim3(OO / BN, ROWS_CAP / BM), 256>>>(x, W2, b2);

    combine_kernel<<<NTOK, 256>>>(out);
}